// round 2
// baseline (speedup 1.0000x reference)
#include <cuda_runtime.h>

#define NSAMP 32
#define OUTP  64
#define MID   8
#define MAXSETS 50000

// ---------------- device scratch (no allocations allowed) ----------------
__device__ double g_stats[4];              // sum t0, sum t1, sum t0^2, sum t1^2
__device__ float  g_c0[3];                 // t0 = tr.x*c0[0] + tr.y*c0[1] + c0[2]
__device__ float  g_c1[3];
__device__ float  g_A[MID][2];             // folded relu(t) -> q coupling
__device__ float  g_bq[MID];               // b_q + Wq . b_p2
__device__ float4 g_buf4[MAXSETS * 4];     // per set: [gsum(8) | res(8)]

// ---------------- packed f32x2 helpers ----------------
__device__ __forceinline__ unsigned long long pk2(float a, float b) {
    unsigned long long r;
    asm("mov.b64 %0, {%1,%2};" : "=l"(r) : "f"(a), "f"(b));
    return r;
}
__device__ __forceinline__ void fma2(unsigned long long &d, unsigned long long a, unsigned long long b) {
    asm("fma.rn.f32x2 %0, %1, %2, %0;" : "+l"(d) : "l"(a), "l"(b));
}
__device__ __forceinline__ float2 upk2(unsigned long long a) {
    float2 r;
    asm("mov.b64 {%0,%1}, %2;" : "=f"(r.x), "=f"(r.y) : "l"(a));
    return r;
}
__device__ __forceinline__ void red4(float4* p, float a, float b, float c, float d) {
    asm volatile("red.global.add.v4.f32 [%0], {%1,%2,%3,%4};"
                 :: "l"(p), "f"(a), "f"(b), "f"(c), "f"(d) : "memory");
}

// ---------------- K0: zero accumulators ----------------
__global__ void k_zero(int nsets) {
    int i = blockIdx.x * blockDim.x + threadIdx.x;
    if (i < 4) g_stats[i] = 0.0;
    if (i < nsets * 4) g_buf4[i] = make_float4(0.f, 0.f, 0.f, 0.f);
}

// ---------------- K1: BatchNorm batch statistics over t = tr @ Wp1^T ----------------
__global__ void k_stats(const float2* __restrict__ tr, const float* __restrict__ Wp1, int N) {
    float w00 = __ldg(Wp1 + 0), w01 = __ldg(Wp1 + 1);
    float w10 = __ldg(Wp1 + 2), w11 = __ldg(Wp1 + 3);
    float s0 = 0.f, s1 = 0.f, q0 = 0.f, q1 = 0.f;
    for (int n = blockIdx.x * blockDim.x + threadIdx.x; n < N; n += gridDim.x * blockDim.x) {
        float2 t = __ldg(&tr[n]);
        float t0 = t.x * w00 + t.y * w01;
        float t1 = t.x * w10 + t.y * w11;
        s0 += t0; s1 += t1; q0 += t0 * t0; q1 += t1 * t1;
    }
    #pragma unroll
    for (int o = 16; o; o >>= 1) {
        s0 += __shfl_xor_sync(0xffffffffu, s0, o);
        s1 += __shfl_xor_sync(0xffffffffu, s1, o);
        q0 += __shfl_xor_sync(0xffffffffu, q0, o);
        q1 += __shfl_xor_sync(0xffffffffu, q1, o);
    }
    if ((threadIdx.x & 31) == 0) {
        atomicAdd(&g_stats[0], (double)s0);
        atomicAdd(&g_stats[1], (double)s1);
        atomicAdd(&g_stats[2], (double)q0);
        atomicAdd(&g_stats[3], (double)q1);
    }
}

// ---------------- K2: fold BN + p-branch into small constants ----------------
__global__ void k_prep(const float* __restrict__ Wq, const float* __restrict__ bq,
                       const float* __restrict__ Wp1, const float* __restrict__ gamma,
                       const float* __restrict__ beta, const float* __restrict__ Wp2,
                       const float* __restrict__ bp2, int N) {
    int t = threadIdx.x;
    if (t < 2) {
        double mean = g_stats[t] / (double)N;
        double var  = g_stats[2 + t] / (double)N - mean * mean;
        float sc = gamma[t] / sqrtf((float)var + 1e-5f);
        float* c = t ? g_c1 : g_c0;
        c[0] = Wp1[t * 2 + 0] * sc;
        c[1] = Wp1[t * 2 + 1] * sc;
        c[2] = beta[t] - (float)mean * sc;
    }
    if (t < MID) {
        float a0 = 0.f, a1 = 0.f, bb = bq[t];
        for (int k = 0; k < OUTP; k++) {
            float w = Wq[t * OUTP + k];
            a0 += w * Wp2[k * 2 + 0];
            a1 += w * Wp2[k * 2 + 1];
            bb += w * bp2[k];
        }
        g_A[t][0] = a0; g_A[t][1] = a1; g_bq[t] = bb;
    }
}

// ---------------- K3: fused main pass (warp = set, lane = sample) ----------------
__global__ void __launch_bounds__(256) k_main(
    const float4* __restrict__ x, const float2* __restrict__ tr,
    const int* __restrict__ idx, const float* __restrict__ Wq,
    const float* __restrict__ Wv, const float* __restrict__ bv,
    float* __restrict__ out, int nsets)
{
    __shared__ float2 sW[MID * OUTP];   // interleaved (Wq[m][k], Wv[m][k])
    int tid = threadIdx.x;
    for (int i = tid; i < MID * OUTP; i += 256)
        sW[i] = make_float2(__ldg(&Wq[i]), __ldg(&Wv[i]));
    __syncthreads();

    int warp = tid >> 5, lane = tid & 31;
    int s = blockIdx.x * 8 + warp;
    if (s >= nsets) return;
    int n = s * NSAMP + lane;

    int   seg = __ldg(&idx[n]);
    float2 t  = __ldg(&tr[n]);
    float t0 = fmaxf(fmaf(t.x, g_c0[0], fmaf(t.y, g_c0[1], g_c0[2])), 0.f);
    float t1 = fmaxf(fmaf(t.x, g_c1[0], fmaf(t.y, g_c1[1], g_c1[2])), 0.f);

    unsigned long long acc[MID];        // .x = q dot, .y = v dot
    #pragma unroll
    for (int m = 0; m < MID; m++) acc[m] = 0ull;

    const float4* xr  = x + (size_t)n * 16;
    const float4* sW4 = (const float4*)sW;   // [MID][32]: 2 (wq,wv) pairs per float4

    #pragma unroll
    for (int c = 0; c < 16; c++) {
        float4 v4 = __ldg(&xr[c]);

        // features[s] = sum over the 32 lanes (samples)
        float fx = v4.x, fy = v4.y, fz = v4.z, fw = v4.w;
        #pragma unroll
        for (int o = 16; o; o >>= 1) {
            fx += __shfl_xor_sync(0xffffffffu, fx, o);
            fy += __shfl_xor_sync(0xffffffffu, fy, o);
            fz += __shfl_xor_sync(0xffffffffu, fz, o);
            fw += __shfl_xor_sync(0xffffffffu, fw, o);
        }
        if (lane == 0)
            ((float4*)out)[(size_t)s * 16 + c] = make_float4(fx, fy, fz, fw);

        unsigned long long x0 = pk2(v4.x, v4.x);
        unsigned long long x1 = pk2(v4.y, v4.y);
        unsigned long long x2 = pk2(v4.z, v4.z);
        unsigned long long x3 = pk2(v4.w, v4.w);
        #pragma unroll
        for (int m = 0; m < MID; m++) {
            float4 wA = sW4[m * 32 + 2 * c];       // (wq,wv) for k=4c, 4c+1
            float4 wB = sW4[m * 32 + 2 * c + 1];   // (wq,wv) for k=4c+2, 4c+3
            fma2(acc[m], x0, pk2(wA.x, wA.y));
            fma2(acc[m], x1, pk2(wA.z, wA.w));
            fma2(acc[m], x2, pk2(wB.x, wB.y));
            fma2(acc[m], x3, pk2(wB.z, wB.w));
        }
    }

    float ev[MID], rv[MID];
    #pragma unroll
    for (int m = 0; m < MID; m++) {
        float2 a  = upk2(acc[m]);
        float qm  = a.x + g_bq[m] + t0 * g_A[m][0] + t1 * g_A[m][1];
        float vm  = a.y + __ldg(&bv[m]);
        float em  = __expf(qm);       // no max-subtraction needed: |q| is O(1)
        ev[m] = em;
        rv[m] = vm * em;
    }
    float4* base = g_buf4 + (size_t)seg * 4;
    red4(base + 0, ev[0], ev[1], ev[2], ev[3]);
    red4(base + 1, ev[4], ev[5], ev[6], ev[7]);
    red4(base + 2, rv[0], rv[1], rv[2], rv[3]);
    red4(base + 3, rv[4], rv[5], rv[6], rv[7]);
}

// ---------------- K4: out = features + tile(res/gsum, 8) ----------------
__global__ void k_final(float* __restrict__ out, int total4) {
    int i = blockIdx.x * blockDim.x + threadIdx.x;
    if (i >= total4) return;
    int s = i >> 4;          // 16 float4 per set
    int h = i & 1;           // which half of the 8-group
    float4 gs = g_buf4[s * 4 + h];
    float4 rs = g_buf4[s * 4 + 2 + h];
    float4 o  = ((float4*)out)[i];
    o.x += rs.x / gs.x;
    o.y += rs.y / gs.y;
    o.z += rs.z / gs.z;
    o.w += rs.w / gs.w;
    ((float4*)out)[i] = o;
}

// ---------------- launch ----------------
extern "C" void kernel_launch(void* const* d_in, const int* in_sizes, int n_in,
                              void* d_out, int out_size) {
    const float* outputs = (const float*)d_in[0];
    const float* transl  = (const float*)d_in[1];
    const int*   idx     = (const int*)  d_in[2];
    const float* Wq      = (const float*)d_in[3];
    const float* bq      = (const float*)d_in[4];
    const float* Wv      = (const float*)d_in[5];
    const float* bv      = (const float*)d_in[6];
    const float* Wp1     = (const float*)d_in[7];
    const float* gamma   = (const float*)d_in[8];
    const float* beta    = (const float*)d_in[9];
    const float* Wp2     = (const float*)d_in[10];
    const float* bp2     = (const float*)d_in[11];

    int N     = in_sizes[2];          // SIZE*NS
    int nsets = out_size / OUTP;      // SIZE

    k_zero <<<(nsets * 4 + 255) / 256, 256>>>(nsets);
    k_stats<<<1024, 256>>>((const float2*)transl, Wp1, N);
    k_prep <<<1, 32>>>(Wq, bq, Wp1, gamma, beta, Wp2, bp2, N);
    k_main <<<(nsets + 7) / 8, 256>>>((const float4*)outputs, (const float2*)transl,
                                      idx, Wq, Wv, bv, (float*)d_out, nsets);
    k_final<<<(nsets * 16 + 255) / 256, 256>>>((float*)d_out, nsets * 16);
}

// round 6
// speedup vs baseline: 1.1897x; 1.1897x over previous
#include <cuda_runtime.h>

#define NSAMP 32
#define OUTP  64
#define MID   8
#define MAXSETS 50000
#define RSET  4    // sets (rows) per thread in k_main

// ---------------- device scratch (no allocations allowed) ----------------
__device__ double g_stats[4];              // sum t0, sum t1, sum t0^2, sum t1^2
__device__ float  g_c0[3];                 // t0 = tr.x*c0[0] + tr.y*c0[1] + c0[2]
__device__ float  g_c1[3];
__device__ float  g_A[MID][2];             // folded relu(t) -> q coupling
__device__ float  g_bq[MID];               // b_q + Wq . b_p2
__device__ float4 g_buf4[MAXSETS * 4];     // per set: [gsum(8) | res(8)]

// ---------------- packed f32x2 helpers ----------------
__device__ __forceinline__ unsigned long long pk2(float a, float b) {
    unsigned long long r;
    asm("mov.b64 %0, {%1,%2};" : "=l"(r) : "f"(a), "f"(b));
    return r;
}
__device__ __forceinline__ void fma2(unsigned long long &d, unsigned long long a, unsigned long long b) {
    asm("fma.rn.f32x2 %0, %1, %2, %0;" : "+l"(d) : "l"(a), "l"(b));
}
__device__ __forceinline__ float2 upk2(unsigned long long a) {
    float2 r;
    asm("mov.b64 {%0,%1}, %2;" : "=f"(r.x), "=f"(r.y) : "l"(a));
    return r;
}
__device__ __forceinline__ void red4(float4* p, float a, float b, float c, float d) {
    asm volatile("red.global.add.v4.f32 [%0], {%1,%2,%3,%4};"
                 :: "l"(p), "f"(a), "f"(b), "f"(c), "f"(d) : "memory");
}

// ---------------- K0: zero accumulators ----------------
__global__ void k_zero(int nsets) {
    int i = blockIdx.x * blockDim.x + threadIdx.x;
    if (i < 4) g_stats[i] = 0.0;
    if (i < nsets * 4) g_buf4[i] = make_float4(0.f, 0.f, 0.f, 0.f);
}

// ---------------- K1: BatchNorm batch statistics over t = tr @ Wp1^T ----------------
__global__ void k_stats(const float2* __restrict__ tr, const float* __restrict__ Wp1, int N) {
    float w00 = __ldg(Wp1 + 0), w01 = __ldg(Wp1 + 1);
    float w10 = __ldg(Wp1 + 2), w11 = __ldg(Wp1 + 3);
    float s0 = 0.f, s1 = 0.f, q0 = 0.f, q1 = 0.f;
    for (int n = blockIdx.x * blockDim.x + threadIdx.x; n < N; n += gridDim.x * blockDim.x) {
        float2 t = __ldg(&tr[n]);
        float t0 = t.x * w00 + t.y * w01;
        float t1 = t.x * w10 + t.y * w11;
        s0 += t0; s1 += t1; q0 += t0 * t0; q1 += t1 * t1;
    }
    #pragma unroll
    for (int o = 16; o; o >>= 1) {
        s0 += __shfl_xor_sync(0xffffffffu, s0, o);
        s1 += __shfl_xor_sync(0xffffffffu, s1, o);
        q0 += __shfl_xor_sync(0xffffffffu, q0, o);
        q1 += __shfl_xor_sync(0xffffffffu, q1, o);
    }
    if ((threadIdx.x & 31) == 0) {
        atomicAdd(&g_stats[0], (double)s0);
        atomicAdd(&g_stats[1], (double)s1);
        atomicAdd(&g_stats[2], (double)q0);
        atomicAdd(&g_stats[3], (double)q1);
    }
}

// ---------------- K2: fold BN + p-branch into small constants ----------------
__global__ void k_prep(const float* __restrict__ Wq, const float* __restrict__ bq,
                       const float* __restrict__ Wp1, const float* __restrict__ gamma,
                       const float* __restrict__ beta, const float* __restrict__ Wp2,
                       const float* __restrict__ bp2, int N) {
    int t = threadIdx.x;
    if (t < 2) {
        double mean = g_stats[t] / (double)N;
        double var  = g_stats[2 + t] / (double)N - mean * mean;
        float sc = gamma[t] / sqrtf((float)var + 1e-5f);
        float* c = t ? g_c1 : g_c0;
        c[0] = Wp1[t * 2 + 0] * sc;
        c[1] = Wp1[t * 2 + 1] * sc;
        c[2] = beta[t] - (float)mean * sc;
    }
    if (t < MID) {
        float a0 = 0.f, a1 = 0.f, bb = bq[t];
        for (int k = 0; k < OUTP; k++) {
            float w = Wq[t * OUTP + k];
            a0 += w * Wp2[k * 2 + 0];
            a1 += w * Wp2[k * 2 + 1];
            bb += w * bp2[k];
        }
        g_A[t][0] = a0; g_A[t][1] = a1; g_bq[t] = bb;
    }
}

// ---------------- K3: fused main pass ----------------
// warp handles RSET=4 sets; lane = sample index within each set (coalesced LDG).
// Each thread: 4 rows share one pass over the weights (weight LDS amortized 4x).
__global__ void __launch_bounds__(256) k_main(
    const float4* __restrict__ x, const float2* __restrict__ tr,
    const int* __restrict__ idx, const float* __restrict__ Wq,
    const float* __restrict__ Wv, const float* __restrict__ bv,
    float* __restrict__ out, int nsets)
{
    __shared__ float2 sW[MID * OUTP];   // interleaved (Wq[m][k], Wv[m][k])
    int tid = threadIdx.x;
    for (int i = tid; i < MID * OUTP; i += 256)
        sW[i] = make_float2(__ldg(&Wq[i]), __ldg(&Wv[i]));
    __syncthreads();

    int warp = tid >> 5, lane = tid & 31;
    int s0 = (blockIdx.x * 8 + warp) * RSET;
    if (s0 >= nsets) return;

    // per-row state
    int   seg[RSET];
    float t0v[RSET], t1v[RSET];
    const float4* xr[RSET];
    #pragma unroll
    for (int r = 0; r < RSET; r++) {
        int n = (s0 + r) * NSAMP + lane;
        seg[r] = __ldg(&idx[n]);
        float2 t = __ldg(&tr[n]);
        t0v[r] = fmaxf(fmaf(t.x, g_c0[0], fmaf(t.y, g_c0[1], g_c0[2])), 0.f);
        t1v[r] = fmaxf(fmaf(t.x, g_c1[0], fmaf(t.y, g_c1[1], g_c1[2])), 0.f);
        xr[r]  = x + (size_t)n * 16;
    }

    unsigned long long acc[RSET][MID];      // .x = q dot, .y = v dot
    #pragma unroll
    for (int r = 0; r < RSET; r++)
        #pragma unroll
        for (int m = 0; m < MID; m++) acc[r][m] = 0ull;

    // [MID][32] ulonglong2 view: each element packs 2 (wq,wv) f32x2 pairs.
    // Row stride per m is 64 float2 = 32 ulonglong2.  (R5 bug was stride 16.)
    const ulonglong2* sWu = (const ulonglong2*)sW;
    const int b0 = lane & 1, b1 = (lane >> 1) & 1;
    const int chsel = (b0 << 1) | b1;       // channel this lane ends with after exchange

    #pragma unroll
    for (int c = 0; c < 16; c++) {
        unsigned long long xd[RSET][4];
        #pragma unroll
        for (int r = 0; r < RSET; r++) {
            float4 v4 = __ldg(&xr[r][c]);

            // ---- features: exchange reduction (6 SHFL instead of 20) ----
            float keepA = b0 ? v4.z : v4.x;
            float keepB = b0 ? v4.w : v4.y;
            float sendA = b0 ? v4.x : v4.z;
            float sendB = b0 ? v4.y : v4.w;
            keepA += __shfl_xor_sync(0xffffffffu, sendA, 1);
            keepB += __shfl_xor_sync(0xffffffffu, sendB, 1);
            float keep = b1 ? keepB : keepA;
            float send = b1 ? keepA : keepB;
            keep += __shfl_xor_sync(0xffffffffu, send, 2);
            keep += __shfl_xor_sync(0xffffffffu, keep, 4);
            keep += __shfl_xor_sync(0xffffffffu, keep, 8);
            keep += __shfl_xor_sync(0xffffffffu, keep, 16);
            if (lane < 4)
                out[((size_t)(s0 + r) * 16 + c) * 4 + chsel] = keep;

            // duplicate-pack x components for f32x2 FMAs
            xd[r][0] = pk2(v4.x, v4.x);
            xd[r][1] = pk2(v4.y, v4.y);
            xd[r][2] = pk2(v4.z, v4.z);
            xd[r][3] = pk2(v4.w, v4.w);
        }

        #pragma unroll
        for (int m = 0; m < MID; m++) {
            ulonglong2 wA = sWu[m * 32 + 2 * c];       // (q,v) for k=4c, 4c+1
            ulonglong2 wB = sWu[m * 32 + 2 * c + 1];   // (q,v) for k=4c+2, 4c+3
            #pragma unroll
            for (int r = 0; r < RSET; r++) {
                fma2(acc[r][m], xd[r][0], wA.x);
                fma2(acc[r][m], xd[r][1], wA.y);
                fma2(acc[r][m], xd[r][2], wB.x);
                fma2(acc[r][m], xd[r][3], wB.y);
            }
        }
    }

    #pragma unroll
    for (int r = 0; r < RSET; r++) {
        float ev[MID], rv[MID];
        #pragma unroll
        for (int m = 0; m < MID; m++) {
            float2 a  = upk2(acc[r][m]);
            float qm  = a.x + g_bq[m] + t0v[r] * g_A[m][0] + t1v[r] * g_A[m][1];
            float vm  = a.y + __ldg(&bv[m]);
            float em  = __expf(qm);     // no max-subtraction needed: |q| is O(1)
            ev[m] = em;
            rv[m] = vm * em;
        }
        float4* base = g_buf4 + (size_t)seg[r] * 4;
        red4(base + 0, ev[0], ev[1], ev[2], ev[3]);
        red4(base + 1, ev[4], ev[5], ev[6], ev[7]);
        red4(base + 2, rv[0], rv[1], rv[2], rv[3]);
        red4(base + 3, rv[4], rv[5], rv[6], rv[7]);
    }
}

// ---------------- K4: out = features + tile(res/gsum, 8) ----------------
__global__ void k_final(float* __restrict__ out, int total4) {
    int i = blockIdx.x * blockDim.x + threadIdx.x;
    if (i >= total4) return;
    int s = i >> 4;          // 16 float4 per set
    int h = i & 1;           // which half of the 8-group
    float4 gs = g_buf4[s * 4 + h];
    float4 rs = g_buf4[s * 4 + 2 + h];
    float4 o  = ((float4*)out)[i];
    o.x += rs.x / gs.x;
    o.y += rs.y / gs.y;
    o.z += rs.z / gs.z;
    o.w += rs.w / gs.w;
    ((float4*)out)[i] = o;
}

// ---------------- launch ----------------
extern "C" void kernel_launch(void* const* d_in, const int* in_sizes, int n_in,
                              void* d_out, int out_size) {
    const float* outputs = (const float*)d_in[0];
    const float* transl  = (const float*)d_in[1];
    const int*   idx     = (const int*)  d_in[2];
    const float* Wq      = (const float*)d_in[3];
    const float* bq      = (const float*)d_in[4];
    const float* Wv      = (const float*)d_in[5];
    const float* bv      = (const float*)d_in[6];
    const float* Wp1     = (const float*)d_in[7];
    const float* gamma   = (const float*)d_in[8];
    const float* beta    = (const float*)d_in[9];
    const float* Wp2     = (const float*)d_in[10];
    const float* bp2     = (const float*)d_in[11];

    int N     = in_sizes[2];          // SIZE*NS
    int nsets = out_size / OUTP;      // SIZE

    k_zero <<<(nsets * 4 + 255) / 256, 256>>>(nsets);
    k_stats<<<1024, 256>>>((const float2*)transl, Wp1, N);
    k_prep <<<1, 32>>>(Wq, bq, Wp1, gamma, beta, Wp2, bp2, N);
    int warps = (nsets + RSET - 1) / RSET;
    k_main <<<(warps + 7) / 8, 256>>>((const float4*)outputs, (const float2*)transl,
                                      idx, Wq, Wv, bv, (float*)d_out, nsets);
    k_final<<<(nsets * 16 + 255) / 256, 256>>>((float*)d_out, nsets * 16);
}

// round 7
// speedup vs baseline: 1.6634x; 1.3982x over previous
#include <cuda_runtime.h>

#define NSAMP 32
#define OUTP  64
#define MID   8
#define MAXSETS 50000

// ---------------- device scratch (zero-initialized at module load) ----------------
__device__ double g_stats[4];              // k_prep re-zeroes after reading
__device__ float  g_c0[3];                 // t0 = tr.x*c0[0] + tr.y*c0[1] + c0[2]
__device__ float  g_c1[3];
__device__ float  g_A[MID][2];             // folded relu(t) -> q coupling
__device__ float  g_bq[MID];               // b_q + Wq . b_p2
__device__ float4 g_buf4[MAXSETS * 4];     // per set: [gsum(8) | res(8)]; k_final re-zeroes

// ---------------- packed f32x2 helpers ----------------
__device__ __forceinline__ unsigned long long pk2(float a, float b) {
    unsigned long long r;
    asm("mov.b64 %0, {%1,%2};" : "=l"(r) : "f"(a), "f"(b));
    return r;
}
__device__ __forceinline__ void fma2(unsigned long long &d, unsigned long long a, unsigned long long b) {
    asm("fma.rn.f32x2 %0, %1, %2, %0;" : "+l"(d) : "l"(a), "l"(b));
}
__device__ __forceinline__ float2 upk2(unsigned long long a) {
    float2 r;
    asm("mov.b64 {%0,%1}, %2;" : "=f"(r.x), "=f"(r.y) : "l"(a));
    return r;
}
__device__ __forceinline__ void red4(float4* p, float a, float b, float c, float d) {
    asm volatile("red.global.add.v4.f32 [%0], {%1,%2,%3,%4};"
                 :: "l"(p), "f"(a), "f"(b), "f"(c), "f"(d) : "memory");
}

// ---------------- K1: BatchNorm batch statistics over t = tr @ Wp1^T ----------------
__global__ void k_stats(const float2* __restrict__ tr, const float* __restrict__ Wp1, int N) {
    float w00 = __ldg(Wp1 + 0), w01 = __ldg(Wp1 + 1);
    float w10 = __ldg(Wp1 + 2), w11 = __ldg(Wp1 + 3);
    float s0 = 0.f, s1 = 0.f, q0 = 0.f, q1 = 0.f;
    for (int n = blockIdx.x * blockDim.x + threadIdx.x; n < N; n += gridDim.x * blockDim.x) {
        float2 t = __ldg(&tr[n]);
        float t0 = t.x * w00 + t.y * w01;
        float t1 = t.x * w10 + t.y * w11;
        s0 += t0; s1 += t1; q0 += t0 * t0; q1 += t1 * t1;
    }
    #pragma unroll
    for (int o = 16; o; o >>= 1) {
        s0 += __shfl_xor_sync(0xffffffffu, s0, o);
        s1 += __shfl_xor_sync(0xffffffffu, s1, o);
        q0 += __shfl_xor_sync(0xffffffffu, q0, o);
        q1 += __shfl_xor_sync(0xffffffffu, q1, o);
    }
    if ((threadIdx.x & 31) == 0) {
        atomicAdd(&g_stats[0], (double)s0);
        atomicAdd(&g_stats[1], (double)s1);
        atomicAdd(&g_stats[2], (double)q0);
        atomicAdd(&g_stats[3], (double)q1);
    }
}

// ---------------- K2: fold BN + p-branch into small constants (re-zero g_stats) -------
__global__ void k_prep(const float* __restrict__ Wq, const float* __restrict__ bq,
                       const float* __restrict__ Wp1, const float* __restrict__ gamma,
                       const float* __restrict__ beta, const float* __restrict__ Wp2,
                       const float* __restrict__ bp2, int N) {
    int t = threadIdx.x;
    if (t < 2) {
        double mean = g_stats[t] / (double)N;
        double var  = g_stats[2 + t] / (double)N - mean * mean;
        float sc = gamma[t] / sqrtf((float)var + 1e-5f);
        float* c = t ? g_c1 : g_c0;
        c[0] = Wp1[t * 2 + 0] * sc;
        c[1] = Wp1[t * 2 + 1] * sc;
        c[2] = beta[t] - (float)mean * sc;
    }
    if (t < MID) {
        float a0 = 0.f, a1 = 0.f, bb = bq[t];
        for (int k = 0; k < OUTP; k++) {
            float w = Wq[t * OUTP + k];
            a0 += w * Wp2[k * 2 + 0];
            a1 += w * Wp2[k * 2 + 1];
            bb += w * bp2[k];
        }
        g_A[t][0] = a0; g_A[t][1] = a1; g_bq[t] = bb;
    }
    __syncwarp();
    if (t < 4) g_stats[t] = 0.0;   // restore zero-invariant for next replay
}

// ---------------- K3: fused main pass ----------------
// Block = 64 threads (2 warps). Warp processes 2 sets:
//   stage: coalesced LDG.128 -> XOR-swizzled smem, features accumulated for free
//   qv:    conflict-free LDS.128 per-sample rows, packed f32x2 dual (q,v) dots
__global__ void __launch_bounds__(64, 6) k_main(
    const float4* __restrict__ x, const float2* __restrict__ tr,
    const int* __restrict__ idx, const float* __restrict__ Wq,
    const float* __restrict__ Wv, const float* __restrict__ bv,
    float* __restrict__ out, int nsets)
{
    __shared__ float2 sW[MID * OUTP];            // 4KB interleaved (Wq,Wv)
    __shared__ float  sX[2][2][NSAMP * OUTP];    // 32KB: [warp][set][sample*64 sw.]

    int tid = threadIdx.x;
    #pragma unroll
    for (int i = tid; i < MID * OUTP; i += 64)
        sW[i] = make_float2(__ldg(&Wq[i]), __ldg(&Wv[i]));
    __syncthreads();

    int warp = tid >> 5, lane = tid & 31;
    int s0 = (blockIdx.x * 2 + warp) * 2;
    if (s0 >= nsets) return;                     // uniform per warp; no later __syncthreads

    // ---------------- staging + features ----------------
    int half = lane >> 4;          // which sample parity this lane loads
    int j    = lane & 15;          // float4 group (channels 4j..4j+3)
    #pragma unroll
    for (int r = 0; r < 2; r++) {
        int sr = min(s0 + r, nsets - 1);         // clamp (duplicate harmless)
        const float4* src = x + (size_t)sr * NSAMP * 16;
        float* dst = sX[warp][r];
        float f0 = 0.f, f1 = 0.f, f2 = 0.f, f3 = 0.f;
        #pragma unroll
        for (int it = 0; it < 16; it++) {
            int s = it * 2 + half;
            float4 v = __ldg(&src[s * 16 + j]);  // warp: 512B contiguous
            f0 += v.x; f1 += v.y; f2 += v.z; f3 += v.w;
            int jp = j ^ (s & 7);                // XOR swizzle
            *(float4*)&dst[s * 64 + jp * 4] = v;
        }
        f0 += __shfl_xor_sync(0xffffffffu, f0, 16);
        f1 += __shfl_xor_sync(0xffffffffu, f1, 16);
        f2 += __shfl_xor_sync(0xffffffffu, f2, 16);
        f3 += __shfl_xor_sync(0xffffffffu, f3, 16);
        if (lane < 16)
            ((float4*)out)[(size_t)sr * 16 + j] = make_float4(f0, f1, f2, f3);
    }
    __syncwarp();

    // ---------------- per-sample metadata ----------------
    int   seg[2];
    float t0v[2], t1v[2];
    #pragma unroll
    for (int r = 0; r < 2; r++) {
        int n = min(s0 + r, nsets - 1) * NSAMP + lane;
        seg[r] = __ldg(&idx[n]);
        float2 t = __ldg(&tr[n]);
        t0v[r] = fmaxf(fmaf(t.x, g_c0[0], fmaf(t.y, g_c0[1], g_c0[2])), 0.f);
        t1v[r] = fmaxf(fmaf(t.x, g_c1[0], fmaf(t.y, g_c1[1], g_c1[2])), 0.f);
    }

    // ---------------- dual (q,v) dot products ----------------
    unsigned long long acc[2][MID];
    #pragma unroll
    for (int r = 0; r < 2; r++)
        #pragma unroll
        for (int m = 0; m < MID; m++) acc[r][m] = 0ull;

    const float* row0 = sX[warp][0] + lane * 64;   // lane = sample
    const float* row1 = sX[warp][1] + lane * 64;
    const int lx = lane & 7;
    const ulonglong2* sWu = (const ulonglong2*)sW; // [m][32]: 2 (wq,wv) pairs each

    #pragma unroll
    for (int c = 0; c < 16; c++) {
        float4 a0 = *(const float4*)&row0[(c ^ lx) * 4];  // conflict-free (swizzle)
        float4 a1 = *(const float4*)&row1[(c ^ lx) * 4];
        unsigned long long x00 = pk2(a0.x, a0.x), x01 = pk2(a0.y, a0.y);
        unsigned long long x02 = pk2(a0.z, a0.z), x03 = pk2(a0.w, a0.w);
        unsigned long long x10 = pk2(a1.x, a1.x), x11 = pk2(a1.y, a1.y);
        unsigned long long x12 = pk2(a1.z, a1.z), x13 = pk2(a1.w, a1.w);
        #pragma unroll
        for (int m = 0; m < MID; m++) {
            ulonglong2 wA = sWu[m * 32 + 2 * c];        // (q,v) for k=4c,4c+1
            ulonglong2 wB = sWu[m * 32 + 2 * c + 1];    // (q,v) for k=4c+2,4c+3
            fma2(acc[0][m], x00, wA.x); fma2(acc[0][m], x01, wA.y);
            fma2(acc[0][m], x02, wB.x); fma2(acc[0][m], x03, wB.y);
            fma2(acc[1][m], x10, wA.x); fma2(acc[1][m], x11, wA.y);
            fma2(acc[1][m], x12, wB.x); fma2(acc[1][m], x13, wB.y);
        }
    }

    // ---------------- epilogue: exp + scatter RED ----------------
    #pragma unroll
    for (int r = 0; r < 2; r++) {
        if (s0 + r >= nsets) break;             // guard duplicates (no double-count)
        float ev[MID], rv[MID];
        #pragma unroll
        for (int m = 0; m < MID; m++) {
            float2 a = upk2(acc[r][m]);
            float qm = a.x + g_bq[m] + t0v[r] * g_A[m][0] + t1v[r] * g_A[m][1];
            float vm = a.y + __ldg(&bv[m]);
            float em = __expf(qm);              // |q| is O(1): no max-subtraction needed
            ev[m] = em;
            rv[m] = vm * em;
        }
        float4* base = g_buf4 + (size_t)seg[r] * 4;
        red4(base + 0, ev[0], ev[1], ev[2], ev[3]);
        red4(base + 1, ev[4], ev[5], ev[6], ev[7]);
        red4(base + 2, rv[0], rv[1], rv[2], rv[3]);
        red4(base + 3, rv[4], rv[5], rv[6], rv[7]);
    }
}

// ---------------- K4: out = features + tile(res/gsum, 8); re-zero g_buf4 ----------------
// Block of 256 covers exactly 16 sets (16 float4 each) -> same-block read/zero with sync.
__global__ void k_final(float* __restrict__ out, int total4) {
    int i = blockIdx.x * blockDim.x + threadIdx.x;
    bool ok = i < total4;
    int s = i >> 4;
    int h = i & 1;
    float4 gs, rs, o;
    if (ok) {
        gs = g_buf4[s * 4 + h];
        rs = g_buf4[s * 4 + 2 + h];
        o  = ((float4*)out)[i];
    }
    __syncthreads();
    if (ok && (i & 15) < 4)
        g_buf4[s * 4 + (i & 15)] = make_float4(0.f, 0.f, 0.f, 0.f);  // zero-invariant
    if (ok) {
        o.x += rs.x / gs.x;
        o.y += rs.y / gs.y;
        o.z += rs.z / gs.z;
        o.w += rs.w / gs.w;
        ((float4*)out)[i] = o;
    }
}

// ---------------- launch ----------------
extern "C" void kernel_launch(void* const* d_in, const int* in_sizes, int n_in,
                              void* d_out, int out_size) {
    const float* outputs = (const float*)d_in[0];
    const float* transl  = (const float*)d_in[1];
    const int*   idx     = (const int*)  d_in[2];
    const float* Wq      = (const float*)d_in[3];
    const float* bq      = (const float*)d_in[4];
    const float* Wv      = (const float*)d_in[5];
    const float* bv      = (const float*)d_in[6];
    const float* Wp1     = (const float*)d_in[7];
    const float* gamma   = (const float*)d_in[8];
    const float* beta    = (const float*)d_in[9];
    const float* Wp2     = (const float*)d_in[10];
    const float* bp2     = (const float*)d_in[11];

    int N     = in_sizes[2];          // SIZE*NS
    int nsets = out_size / OUTP;      // SIZE

    k_stats<<<512, 256>>>((const float2*)transl, Wp1, N);
    k_prep <<<1, 32>>>(Wq, bq, Wp1, gamma, beta, Wp2, bp2, N);
    int blocks = (nsets + 3) / 4;     // 2 warps/block * 2 sets/warp
    k_main <<<blocks, 64>>>((const float4*)outputs, (const float2*)transl,
                            idx, Wq, Wv, bv, (float*)d_out, nsets);
    k_final<<<(nsets * 16 + 255) / 256, 256>>>((float*)d_out, nsets * 16);
}